// round 6
// baseline (speedup 1.0000x reference)
#include <cuda_runtime.h>
#include <cuda_bf16.h>
#include <cstdint>

#define NNODES 50000
#define NEDGES 800000
#define HDIM   96

typedef unsigned long long u64;
typedef unsigned int u32;

// ---------------- scratch ----------------
__device__ __align__(128) float g_bufA[NNODES * HDIM];
__device__ __align__(128) float g_bufB[NNODES * HDIM];
__device__ __align__(128) float g_bufC[NNODES * HDIM];
__device__ __align__(128) float g_bufD[NNODES * HDIM];
__device__ __align__(128) float g_Wc[2][HDIM * HDIM];
__device__ __align__(128) float g_bc[2][HDIM];
__device__ int   g_deg[NNODES];
__device__ float g_dis[NNODES];
__device__ float g_invdeg[NNODES];
__device__ int   g_row_ptr[NNODES + 1];
__device__ int   g_cursor[NNODES];
__device__ int   g_csr_src[NEDGES];
__device__ int   g_part[128];

// ---------------- graph build ----------------
__global__ void k_zero_deg() {
    int i = blockIdx.x * blockDim.x + threadIdx.x;
    if (i < NNODES) g_deg[i] = 0;
}
__global__ void k_hist(const int* __restrict__ dst) {
    int i = blockIdx.x * blockDim.x + threadIdx.x;
    if (i < NEDGES) atomicAdd(&g_deg[dst[i]], 1);
}

#define SCAN_B 512
#define SCAN_NBLK ((NNODES + SCAN_B - 1) / SCAN_B)

__global__ void k_scan_part() {
    __shared__ int ws[16];
    int i = blockIdx.x * SCAN_B + threadIdx.x;
    int v = (i < NNODES) ? g_deg[i] : 0;
    int lane = threadIdx.x & 31, wid = threadIdx.x >> 5;
    int s = v;
    #pragma unroll
    for (int o = 16; o > 0; o >>= 1) s += __shfl_down_sync(0xffffffffu, s, o);
    if (lane == 0) ws[wid] = s;
    __syncthreads();
    if (wid == 0) {
        int t = (lane < (SCAN_B / 32)) ? ws[lane] : 0;
        #pragma unroll
        for (int o = 16; o > 0; o >>= 1) t += __shfl_down_sync(0xffffffffu, t, o);
        if (lane == 0) g_part[blockIdx.x] = t;
    }
}
__global__ void k_scan_mid() {           // 1 warp, shfl scan over SCAN_NBLK partials
    int lane = threadIdx.x;
    int carry = 0;
    for (int base = 0; base < SCAN_NBLK; base += 32) {
        int i = base + lane;
        int v = (i < SCAN_NBLK) ? g_part[i] : 0;
        int x = v;
        #pragma unroll
        for (int o = 1; o < 32; o <<= 1) {
            int y = __shfl_up_sync(0xffffffffu, x, o);
            if (lane >= o) x += y;
        }
        if (i < SCAN_NBLK) g_part[i] = carry + x - v;
        carry += __shfl_sync(0xffffffffu, x, 31);
    }
    if (lane == 0) g_row_ptr[NNODES] = carry;
}
__global__ void k_scan_apply() {
    __shared__ int ws[17];
    int i = blockIdx.x * SCAN_B + threadIdx.x;
    int v = (i < NNODES) ? g_deg[i] : 0;
    int lane = threadIdx.x & 31, wid = threadIdx.x >> 5;
    int x = v;
    #pragma unroll
    for (int o = 1; o < 32; o <<= 1) {
        int y = __shfl_up_sync(0xffffffffu, x, o);
        if (lane >= o) x += y;
    }
    if (lane == 31) ws[wid] = x;
    __syncthreads();
    if (wid == 0) {
        int nw = SCAN_B / 32;
        int s = (lane < nw) ? ws[lane] : 0;
        #pragma unroll
        for (int o = 1; o < 32; o <<= 1) {
            int y = __shfl_up_sync(0xffffffffu, s, o);
            if (lane >= o) s += y;
        }
        if (lane < nw) ws[lane] = s;
    }
    __syncthreads();
    int excl = x - v + (wid > 0 ? ws[wid - 1] : 0) + g_part[blockIdx.x];
    if (i < NNODES) {
        g_row_ptr[i] = excl;
        g_cursor[i] = excl;
        float d = (float)(v + 1);
        g_dis[i] = rsqrtf(d);
        g_invdeg[i] = 1.0f / d;
    }
}
__global__ void k_scatter(const int* __restrict__ src, const int* __restrict__ dst) {
    int i = blockIdx.x * blockDim.x + threadIdx.x;
    if (i < NEDGES) {
        int d = dst[i];
        int p = atomicAdd(&g_cursor[d], 1);
        g_csr_src[p] = src[i];
    }
}

// ---------------- weight compose: Wc = convW @ preW ; bc = convW @ (pre_b + emb[t]) ----
__global__ void k_compose(const float* __restrict__ preW, const float* __restrict__ pre_b,
                          const float* __restrict__ convW,
                          const float* __restrict__ emb, const int* __restrict__ t,
                          float* __restrict__ Wc, float* __restrict__ bc)
{
    __shared__ float cw[HDIM];
    __shared__ float red[HDIM];
    int j = blockIdx.x, k = threadIdx.x;
    cw[k] = convW[j * HDIM + k];
    __syncthreads();
    float acc = 0.f;
    #pragma unroll 4
    for (int m = 0; m < HDIM; m++) acc += cw[m] * preW[m * HDIM + k];
    Wc[j * HDIM + k] = acc;
    int t0 = t[0];
    red[k] = cw[k] * (pre_b[k] + emb[t0 * HDIM + k]);
    __syncthreads();
    if (k == 0) {
        float s = 0.f;
        for (int m = 0; m < HDIM; m++) s += red[m];
        bc[j] = s;
    }
}

// ---------------- mma.sync bf16-split GEMM pieces ----------------
enum { F_BIAS = 1, F_RELU = 4, F_RES = 8 };

__device__ __forceinline__ void mma16816(float* c, const u32* a, const u32* b) {
    asm volatile(
        "mma.sync.aligned.m16n8k16.row.col.f32.bf16.bf16.f32 "
        "{%0,%1,%2,%3}, {%4,%5,%6,%7}, {%8,%9}, {%0,%1,%2,%3};"
        : "+f"(c[0]), "+f"(c[1]), "+f"(c[2]), "+f"(c[3])
        : "r"(a[0]), "r"(a[1]), "r"(a[2]), "r"(a[3]), "r"(b[0]), "r"(b[1]));
}
__device__ __forceinline__ u32 pack_hi(float f0, float f1) {
    __nv_bfloat162 p;
    p.x = __float2bfloat16(f0);
    p.y = __float2bfloat16(f1);
    return *reinterpret_cast<u32*>(&p);
}
__device__ __forceinline__ u32 pack_lo(float f0, float f1) {
    __nv_bfloat162 p;
    __nv_bfloat16 h0 = __float2bfloat16(f0), h1 = __float2bfloat16(f1);
    p.x = __float2bfloat16(f0 - __bfloat162float(h0));
    p.y = __float2bfloat16(f1 - __bfloat162float(h1));
    return *reinterpret_cast<u32*>(&p);
}

#define STR 208   // smem row stride (bytes): 52 words -> conflict-free frag loads

// stage a [rows x 96] fp32 matrix as hi/lo bf16 tiles
__device__ __forceinline__ void stage_hi_lo(
    const float* __restrict__ src, char* smh, char* sml,
    int rows, int r0, int nrows, int tid, int nthr)
{
    for (int i = tid; i < rows * 12; i += nthr) {
        int row = i / 12, col = (i - row * 12) * 8;
        if (r0 + row < nrows) {
            const float4* p = reinterpret_cast<const float4*>(src + (size_t)(r0 + row) * HDIM + col);
            float4 v0 = p[0], v1 = p[1];
            float xs[8] = {v0.x, v0.y, v0.z, v0.w, v1.x, v1.y, v1.z, v1.w};
            uint4 hw, lw;
            hw.x = pack_hi(xs[0], xs[1]); hw.y = pack_hi(xs[2], xs[3]);
            hw.z = pack_hi(xs[4], xs[5]); hw.w = pack_hi(xs[6], xs[7]);
            lw.x = pack_lo(xs[0], xs[1]); lw.y = pack_lo(xs[2], xs[3]);
            lw.z = pack_lo(xs[4], xs[5]); lw.w = pack_lo(xs[6], xs[7]);
            *reinterpret_cast<uint4*>(smh + row * STR + col * 2) = hw;
            *reinterpret_cast<uint4*>(sml + row * STR + col * 2) = lw;
        }
    }
}

// compute 3-term split MMA over K=96 for this warp's 16-row stripe
template <int NT>
__device__ __forceinline__ void mma_pass(
    const char* xh, const char* xl, const char* wmh, const char* wml,
    int g, int tg, float acc[][4])
{
    #pragma unroll
    for (int kc = 0; kc < 6; kc++) {
        int o0 = (kc * 16 + 2 * tg) * 2;
        int o8 = o0 + 16;
        u32 ah[4], al[4];
        ah[0] = *reinterpret_cast<const u32*>(xh + o0);
        ah[1] = *reinterpret_cast<const u32*>(xh + 8 * STR + o0);
        ah[2] = *reinterpret_cast<const u32*>(xh + o8);
        ah[3] = *reinterpret_cast<const u32*>(xh + 8 * STR + o8);
        al[0] = *reinterpret_cast<const u32*>(xl + o0);
        al[1] = *reinterpret_cast<const u32*>(xl + 8 * STR + o0);
        al[2] = *reinterpret_cast<const u32*>(xl + o8);
        al[3] = *reinterpret_cast<const u32*>(xl + 8 * STR + o8);
        #pragma unroll
        for (int nt = 0; nt < NT; nt++) {
            const char* wh = wmh + (nt * 8 + g) * STR;
            const char* wl = wml + (nt * 8 + g) * STR;
            u32 bh[2], bl[2];
            bh[0] = *reinterpret_cast<const u32*>(wh + o0);
            bh[1] = *reinterpret_cast<const u32*>(wh + o8);
            bl[0] = *reinterpret_cast<const u32*>(wl + o0);
            bl[1] = *reinterpret_cast<const u32*>(wl + o8);
            mma16816(acc[nt], ah, bh);
            mma16816(acc[nt], ah, bl);
            mma16816(acc[nt], al, bh);
        }
    }
}

// ---------------- single GEMM kernel ----------------
template <int HOUT, unsigned FLAGS>
__global__ void __launch_bounds__(256) k_mma(
    const float* __restrict__ in, const float* __restrict__ W,
    const float* __restrict__ bias, const float* __restrict__ res,
    float* __restrict__ out, int nrows)
{
    const int NT = HOUT / 8;
    const int SM_XH = 0, SM_XL = 128 * STR;
    const int SM_WH = 2 * 128 * STR, SM_WL = SM_WH + HOUT * STR;
    extern __shared__ char sm[];
    int tid = threadIdx.x;
    int r0 = blockIdx.x * 128;

    stage_hi_lo(in, sm + SM_XH, sm + SM_XL, 128, r0, nrows, tid, 256);
    stage_hi_lo(W,  sm + SM_WH, sm + SM_WL, HOUT, 0, HOUT, tid, 256);
    __syncthreads();

    int w = tid >> 5, lane = tid & 31;
    int g = lane >> 2, tg = lane & 3;

    float acc[NT][4];
    #pragma unroll
    for (int nt = 0; nt < NT; nt++) { acc[nt][0] = acc[nt][1] = acc[nt][2] = acc[nt][3] = 0.f; }

    mma_pass<NT>(sm + SM_XH + (w * 16 + g) * STR, sm + SM_XL + (w * 16 + g) * STR,
                 sm + SM_WH, sm + SM_WL, g, tg, acc);

    int row0 = r0 + w * 16 + g, row1 = row0 + 8;
    #pragma unroll
    for (int nt = 0; nt < NT; nt++) {
        int n0 = nt * 8 + 2 * tg;
        float2 bv = make_float2(0.f, 0.f);
        if (FLAGS & F_BIAS) bv = *reinterpret_cast<const float2*>(bias + n0);
        if (row0 < nrows) {
            float v0 = acc[nt][0] + bv.x, v1 = acc[nt][1] + bv.y;
            if (FLAGS & F_RELU) { v0 = fmaxf(v0, 0.f); v1 = fmaxf(v1, 0.f); }
            if (FLAGS & F_RES) {
                float2 rv = *reinterpret_cast<const float2*>(res + (size_t)row0 * HOUT + n0);
                v0 += rv.x; v1 += rv.y;
            }
            *reinterpret_cast<float2*>(out + (size_t)row0 * HOUT + n0) = make_float2(v0, v1);
        }
        if (row1 < nrows) {
            float v0 = acc[nt][2] + bv.x, v1 = acc[nt][3] + bv.y;
            if (FLAGS & F_RELU) { v0 = fmaxf(v0, 0.f); v1 = fmaxf(v1, 0.f); }
            if (FLAGS & F_RES) {
                float2 rv = *reinterpret_cast<const float2*>(res + (size_t)row1 * HOUT + n0);
                v0 += rv.x; v1 += rv.y;
            }
            *reinterpret_cast<float2*>(out + (size_t)row1 * HOUT + n0) = make_float2(v0, v1);
        }
    }
}

// ---------------- fused post-MLP: out = relu(in@W1^T+b1)@W2^T + b2 + res ----------------
__global__ void __launch_bounds__(256) k_mma2(
    const float* __restrict__ in,
    const float* __restrict__ W1, const float* __restrict__ b1,
    const float* __restrict__ W2, const float* __restrict__ b2,
    const float* __restrict__ res, float* __restrict__ out, int nrows)
{
    const int NT = 12;
    const int SM_XH  = 0, SM_XL = 128 * STR;               // 0, 26624
    const int SM_W1H = 2 * 128 * STR;                      // 53248
    const int SM_W1L = SM_W1H + 96 * STR;                  // 73216
    const int SM_W2H = SM_W1L + 96 * STR;                  // 93184
    const int SM_W2L = SM_W2H + 96 * STR;                  // 113152 (total 133120)
    extern __shared__ char sm[];
    int tid = threadIdx.x;
    int r0 = blockIdx.x * 128;

    stage_hi_lo(in, sm + SM_XH,  sm + SM_XL,  128, r0, nrows, tid, 256);
    stage_hi_lo(W1, sm + SM_W1H, sm + SM_W1L, 96, 0, 96, tid, 256);
    stage_hi_lo(W2, sm + SM_W2H, sm + SM_W2L, 96, 0, 96, tid, 256);
    __syncthreads();

    int w = tid >> 5, lane = tid & 31;
    int g = lane >> 2, tg = lane & 3;
    const int xoff = (w * 16 + g) * STR;

    float acc[NT][4];
    #pragma unroll
    for (int nt = 0; nt < NT; nt++) { acc[nt][0] = acc[nt][1] = acc[nt][2] = acc[nt][3] = 0.f; }

    // stage 1: H1 = relu(in @ W1^T + b1)
    mma_pass<NT>(sm + SM_XH + xoff, sm + SM_XL + xoff, sm + SM_W1H, sm + SM_W1L, g, tg, acc);
    __syncthreads();   // all warps done reading X; safe to overwrite

    // write H1 (relu'd) back as hi/lo bf16 into X tiles
    #pragma unroll
    for (int nt = 0; nt < NT; nt++) {
        int n0 = nt * 8 + 2 * tg;
        float2 bv = *reinterpret_cast<const float2*>(b1 + n0);
        float v0 = fmaxf(acc[nt][0] + bv.x, 0.f), v1 = fmaxf(acc[nt][1] + bv.y, 0.f);
        float v2 = fmaxf(acc[nt][2] + bv.x, 0.f), v3 = fmaxf(acc[nt][3] + bv.y, 0.f);
        int ra = (w * 16 + g) * STR + n0 * 2;
        int rb = (w * 16 + g + 8) * STR + n0 * 2;
        *reinterpret_cast<u32*>(sm + SM_XH + ra) = pack_hi(v0, v1);
        *reinterpret_cast<u32*>(sm + SM_XL + ra) = pack_lo(v0, v1);
        *reinterpret_cast<u32*>(sm + SM_XH + rb) = pack_hi(v2, v3);
        *reinterpret_cast<u32*>(sm + SM_XL + rb) = pack_lo(v2, v3);
    }
    __syncthreads();

    #pragma unroll
    for (int nt = 0; nt < NT; nt++) { acc[nt][0] = acc[nt][1] = acc[nt][2] = acc[nt][3] = 0.f; }

    // stage 2: out = H1 @ W2^T + b2 + res
    mma_pass<NT>(sm + SM_XH + xoff, sm + SM_XL + xoff, sm + SM_W2H, sm + SM_W2L, g, tg, acc);

    int row0 = r0 + w * 16 + g, row1 = row0 + 8;
    #pragma unroll
    for (int nt = 0; nt < NT; nt++) {
        int n0 = nt * 8 + 2 * tg;
        float2 bv = *reinterpret_cast<const float2*>(b2 + n0);
        if (row0 < nrows) {
            float2 rv = *reinterpret_cast<const float2*>(res + (size_t)row0 * HDIM + n0);
            *reinterpret_cast<float2*>(out + (size_t)row0 * HDIM + n0) =
                make_float2(acc[nt][0] + bv.x + rv.x, acc[nt][1] + bv.y + rv.y);
        }
        if (row1 < nrows) {
            float2 rv = *reinterpret_cast<const float2*>(res + (size_t)row1 * HDIM + n0);
            *reinterpret_cast<float2*>(out + (size_t)row1 * HDIM + n0) =
                make_float2(acc[nt][2] + bv.x + rv.x, acc[nt][3] + bv.y + rv.y);
        }
    }
}

// ---------------- GCN aggregation: one warp per dst node ----------------
__global__ void k_agg(const float* __restrict__ xw, const float* __restrict__ bias,
                      float* __restrict__ out)
{
    int warp = (blockIdx.x * blockDim.x + threadIdx.x) >> 5;
    int lane = threadIdx.x & 31;
    if (warp >= NNODES) return;
    int v = warp;
    int s = g_row_ptr[v], e = g_row_ptr[v + 1];
    float a0 = 0.f, a1 = 0.f, a2 = 0.f;
    int i = s;
    for (; i + 1 < e; i += 2) {
        int u0 = g_csr_src[i], u1 = g_csr_src[i + 1];
        float w0 = g_dis[u0], w1 = g_dis[u1];
        const float* r0p = xw + (size_t)u0 * HDIM;
        const float* r1p = xw + (size_t)u1 * HDIM;
        float x0 = r0p[lane], x1 = r0p[lane + 32], x2 = r0p[lane + 64];
        float y0 = r1p[lane], y1 = r1p[lane + 32], y2 = r1p[lane + 64];
        a0 += w0 * x0 + w1 * y0;
        a1 += w0 * x1 + w1 * y1;
        a2 += w0 * x2 + w1 * y2;
    }
    if (i < e) {
        int u = g_csr_src[i];
        float wn = g_dis[u];
        const float* r = xw + (size_t)u * HDIM;
        a0 += wn * r[lane];
        a1 += wn * r[lane + 32];
        a2 += wn * r[lane + 64];
    }
    float dv = g_dis[v];
    float iv = g_invdeg[v];
    const float* sr = xw + (size_t)v * HDIM;
    float* o = out + (size_t)v * HDIM;
    o[lane]      = a0 * dv + sr[lane]      * iv + bias[lane];
    o[lane + 32] = a1 * dv + sr[lane + 32] * iv + bias[lane + 32];
    o[lane + 64] = a2 * dv + sr[lane + 64] * iv + bias[lane + 64];
}

// ---------------- launch ----------------
extern "C" void kernel_launch(void* const* d_in, const int* in_sizes, int n_in,
                              void* d_out, int out_size)
{
    const float* x       = (const float*)d_in[0];
    const int*   t       = (const int*)  d_in[1];
    const int*   ei      = (const int*)  d_in[2];
    const float* emb     = (const float*)d_in[3];
    const float* fw_W    = (const float*)d_in[4];
    const float* fw_b    = (const float*)d_in[5];
    const float* pre_W   = (const float*)d_in[6];
    const float* pre_b   = (const float*)d_in[7];
    const float* conv_W  = (const float*)d_in[8];
    const float* conv_b  = (const float*)d_in[9];
    const float* post_W1 = (const float*)d_in[10];
    const float* post_b1 = (const float*)d_in[11];
    const float* post_W2 = (const float*)d_in[12];
    const float* post_b2 = (const float*)d_in[13];
    const float* fin_W   = (const float*)d_in[14];
    const float* fin_b   = (const float*)d_in[15];
    float* out = (float*)d_out;

    const int* src = ei;
    const int* dst = ei + NEDGES;

    float *A, *B, *C, *D, *Wc, *bc;
    cudaGetSymbolAddress((void**)&A,  g_bufA);
    cudaGetSymbolAddress((void**)&B,  g_bufB);
    cudaGetSymbolAddress((void**)&C,  g_bufC);
    cudaGetSymbolAddress((void**)&D,  g_bufD);
    cudaGetSymbolAddress((void**)&Wc, g_Wc);
    cudaGetSymbolAddress((void**)&bc, g_bc);

    const int SMEM96  = 2 * 128 * STR + 2 * 96 * STR;          // 93184
    const int SMEM32  = 2 * 128 * STR + 2 * 32 * STR;          // 66560
    const int SMEM2   = 2 * 128 * STR + 6 * 96 * STR;          // 133120
    cudaFuncSetAttribute(k_mma<96, F_BIAS>,          cudaFuncAttributeMaxDynamicSharedMemorySize, SMEM96);
    cudaFuncSetAttribute(k_mma<32, F_BIAS>,          cudaFuncAttributeMaxDynamicSharedMemorySize, SMEM32);
    cudaFuncSetAttribute(k_mma2,                     cudaFuncAttributeMaxDynamicSharedMemorySize, SMEM2);

    // fork: graph build on side stream, GEMM front-end on capture (null) stream
    cudaStream_t s2;
    cudaEvent_t eF, eJ;
    cudaStreamCreateWithFlags(&s2, cudaStreamNonBlocking);
    cudaEventCreateWithFlags(&eF, cudaEventDisableTiming);
    cudaEventCreateWithFlags(&eJ, cudaEventDisableTiming);

    cudaEventRecord(eF, 0);
    cudaStreamWaitEvent(s2, eF, 0);
    k_zero_deg  <<<(NNODES + 255) / 256, 256, 0, s2>>>();
    k_hist      <<<(NEDGES + 255) / 256, 256, 0, s2>>>(dst);
    k_scan_part <<<SCAN_NBLK, SCAN_B, 0, s2>>>();
    k_scan_mid  <<<1, 32, 0, s2>>>();
    k_scan_apply<<<SCAN_NBLK, SCAN_B, 0, s2>>>();
    k_scatter   <<<(NEDGES + 255) / 256, 256, 0, s2>>>(src, dst);
    cudaEventRecord(eJ, s2);

    const int GG = (NNODES + 127) / 128;
    const int AGG_BLOCKS = (NNODES * 32 + 255) / 256;

    // null stream: composes + first GEMM + layer-0 pre GEMM (independent of graph)
    k_compose<<<HDIM, HDIM>>>(pre_W,                pre_b,        conv_W,               emb, t, Wc,               bc);
    k_compose<<<HDIM, HDIM>>>(pre_W + HDIM * HDIM,  pre_b + HDIM, conv_W + HDIM * HDIM, emb, t, Wc + HDIM * HDIM, bc + HDIM);
    k_mma<96, F_BIAS><<<GG, 256, SMEM96>>>(x, fw_W, fw_b, nullptr, A, NNODES);
    k_mma<96, F_BIAS><<<GG, 256, SMEM96>>>(A, Wc, bc, nullptr, C, NNODES);

    cudaStreamWaitEvent(0, eJ, 0);   // join graph build before aggregation

    // layer 0
    k_agg<<<AGG_BLOCKS, 256>>>(C, conv_b, D);
    k_mma2<<<GG, 256, SMEM2>>>(D, post_W1, post_b1, post_W2, post_b2, A, B, NNODES);

    // layer 1
    k_mma<96, F_BIAS><<<GG, 256, SMEM96>>>(B, Wc + HDIM * HDIM, bc + HDIM, nullptr, C, NNODES);
    k_agg<<<AGG_BLOCKS, 256>>>(C, conv_b + HDIM, D);
    k_mma2<<<GG, 256, SMEM2>>>(D, post_W1 + HDIM * HDIM, post_b1 + HDIM,
                               post_W2 + HDIM * HDIM, post_b2 + HDIM, B, C, NNODES);

    // final
    k_mma<32, F_BIAS><<<GG, 256, SMEM32>>>(C, fin_W, fin_b, nullptr, out, NNODES);
}

// round 7
// speedup vs baseline: 1.0071x; 1.0071x over previous
#include <cuda_runtime.h>
#include <cuda_bf16.h>
#include <cstdint>

#define NNODES 50000
#define NEDGES 800000
#define HDIM   96

typedef unsigned long long u64;
typedef unsigned int u32;

// ---------------- scratch ----------------
__device__ __align__(128) float g_bufA[NNODES * HDIM];
__device__ __align__(128) float g_bufB[NNODES * HDIM];
__device__ __align__(128) float g_bufC[NNODES * HDIM];
__device__ __align__(128) float g_bufD[NNODES * HDIM];
__device__ __align__(128) float g_Wc[2][HDIM * HDIM];
__device__ __align__(128) float g_bc[2][HDIM];
__device__ int   g_deg[NNODES];
__device__ float g_dis[NNODES];
__device__ float g_invdeg[NNODES];
__device__ int   g_row_ptr[NNODES + 1];
__device__ int   g_cursor[NNODES];
__device__ int   g_csr_src[NEDGES];
__device__ int   g_part[128];

// ---------------- graph build ----------------
__global__ void k_zero_deg() {
    int i = blockIdx.x * blockDim.x + threadIdx.x;
    if (i < NNODES) g_deg[i] = 0;
}
__global__ void k_hist(const int* __restrict__ dst) {
    int i = blockIdx.x * blockDim.x + threadIdx.x;
    if (i < NEDGES) atomicAdd(&g_deg[dst[i]], 1);
}

#define SCAN_B 512
#define SCAN_NBLK ((NNODES + SCAN_B - 1) / SCAN_B)   // 98

__global__ void k_scan_part() {
    __shared__ int ws[16];
    int i = blockIdx.x * SCAN_B + threadIdx.x;
    int v = (i < NNODES) ? g_deg[i] : 0;
    int lane = threadIdx.x & 31, wid = threadIdx.x >> 5;
    int s = v;
    #pragma unroll
    for (int o = 16; o > 0; o >>= 1) s += __shfl_down_sync(0xffffffffu, s, o);
    if (lane == 0) ws[wid] = s;
    __syncthreads();
    if (wid == 0) {
        int t = (lane < (SCAN_B / 32)) ? ws[lane] : 0;
        #pragma unroll
        for (int o = 16; o > 0; o >>= 1) t += __shfl_down_sync(0xffffffffu, t, o);
        if (lane == 0) g_part[blockIdx.x] = t;
    }
}
__global__ void k_scan_mid() {          // 128 thr, one pass (SCAN_NBLK <= 128)
    __shared__ int ws[4];
    int lane = threadIdx.x & 31, wid = threadIdx.x >> 5;
    int i = threadIdx.x;
    int v = (i < SCAN_NBLK) ? g_part[i] : 0;
    int x = v;
    #pragma unroll
    for (int o = 1; o < 32; o <<= 1) {
        int y = __shfl_up_sync(0xffffffffu, x, o);
        if (lane >= o) x += y;
    }
    if (lane == 31) ws[wid] = x;
    __syncthreads();
    int woff = 0;
    #pragma unroll
    for (int q = 0; q < 4; q++) if (q < wid) woff += ws[q];
    if (i < SCAN_NBLK) g_part[i] = woff + x - v;
    if (i == 127) g_row_ptr[NNODES] = woff + x;
}
__global__ void k_scan_apply() {
    __shared__ int ws[17];
    int i = blockIdx.x * SCAN_B + threadIdx.x;
    int v = (i < NNODES) ? g_deg[i] : 0;
    int lane = threadIdx.x & 31, wid = threadIdx.x >> 5;
    int x = v;
    #pragma unroll
    for (int o = 1; o < 32; o <<= 1) {
        int y = __shfl_up_sync(0xffffffffu, x, o);
        if (lane >= o) x += y;
    }
    if (lane == 31) ws[wid] = x;
    __syncthreads();
    if (wid == 0) {
        int nw = SCAN_B / 32;
        int s = (lane < nw) ? ws[lane] : 0;
        #pragma unroll
        for (int o = 1; o < 32; o <<= 1) {
            int y = __shfl_up_sync(0xffffffffu, s, o);
            if (lane >= o) s += y;
        }
        if (lane < nw) ws[lane] = s;
    }
    __syncthreads();
    int excl = x - v + (wid > 0 ? ws[wid - 1] : 0) + g_part[blockIdx.x];
    if (i < NNODES) {
        g_row_ptr[i] = excl;
        g_cursor[i] = excl;
        float d = (float)(v + 1);
        g_dis[i] = rsqrtf(d);
        g_invdeg[i] = 1.0f / d;
    }
}
__global__ void k_scatter(const int* __restrict__ src, const int* __restrict__ dst) {
    int i = blockIdx.x * blockDim.x + threadIdx.x;
    if (i < NEDGES) {
        int d = dst[i];
        int p = atomicAdd(&g_cursor[d], 1);
        g_csr_src[p] = src[i];
    }
}

// ---------------- weight compose (both layers, one launch) ----------------
__global__ void k_compose2(const float* __restrict__ preW, const float* __restrict__ pre_b,
                           const float* __restrict__ convW,
                           const float* __restrict__ emb, const int* __restrict__ t)
{
    __shared__ float cw[HDIM];
    __shared__ float red[HDIM];
    int l = blockIdx.y;
    const float* pW = preW + l * HDIM * HDIM;
    const float* pb = pre_b + l * HDIM;
    const float* cW = convW + l * HDIM * HDIM;
    int j = blockIdx.x, k = threadIdx.x;
    cw[k] = cW[j * HDIM + k];
    __syncthreads();
    float acc = 0.f;
    #pragma unroll 4
    for (int m = 0; m < HDIM; m++) acc += cw[m] * pW[m * HDIM + k];
    g_Wc[l][j * HDIM + k] = acc;
    int t0 = t[0];
    red[k] = cw[k] * (pb[k] + emb[t0 * HDIM + k]);
    __syncthreads();
    if (k == 0) {
        float s = 0.f;
        for (int m = 0; m < HDIM; m++) s += red[m];
        g_bc[l][j] = s;
    }
}

// ---------------- mma.sync bf16-split GEMM pieces ----------------
enum { F_BIAS = 1, F_RELU = 4, F_RES = 8 };
#define WSTR 200   // W/H1 smem row stride (50 words)

__device__ __forceinline__ void mma16816(float* c, const u32* a, const u32* b) {
    asm volatile(
        "mma.sync.aligned.m16n8k16.row.col.f32.bf16.bf16.f32 "
        "{%0,%1,%2,%3}, {%4,%5,%6,%7}, {%8,%9}, {%0,%1,%2,%3};"
        : "+f"(c[0]), "+f"(c[1]), "+f"(c[2]), "+f"(c[3])
        : "r"(a[0]), "r"(a[1]), "r"(a[2]), "r"(a[3]), "r"(b[0]), "r"(b[1]));
}
__device__ __forceinline__ u32 pack_hi(float f0, float f1) {
    __nv_bfloat162 p;
    p.x = __float2bfloat16(f0);
    p.y = __float2bfloat16(f1);
    return *reinterpret_cast<u32*>(&p);
}
__device__ __forceinline__ u32 pack_lo(float f0, float f1) {
    __nv_bfloat162 p;
    __nv_bfloat16 h0 = __float2bfloat16(f0), h1 = __float2bfloat16(f1);
    p.x = __float2bfloat16(f0 - __bfloat162float(h0));
    p.y = __float2bfloat16(f1 - __bfloat162float(h1));
    return *reinterpret_cast<u32*>(&p);
}

// stage a [rows x 96] fp32 weight matrix as hi/lo bf16 planes (k-natural layout;
// fragments use the k-permuted mapping: lane tg covers k = 4tg..4tg+3 of each 16-chunk)
__device__ __forceinline__ void stage_w(const float* __restrict__ W,
                                        char* wh, char* wl, int rows, int tid)
{
    for (int i = tid; i < rows * 24; i += 256) {
        int row = i / 24, q = i - row * 24;
        float4 v = *reinterpret_cast<const float4*>(W + row * 96 + q * 4);
        *reinterpret_cast<uint2*>(wh + row * WSTR + q * 8) =
            make_uint2(pack_hi(v.x, v.y), pack_hi(v.z, v.w));
        *reinterpret_cast<uint2*>(wl + row * WSTR + q * 8) =
            make_uint2(pack_lo(v.x, v.y), pack_lo(v.z, v.w));
    }
}

// A-fragments (hi+lo) for one k-chunk, loaded straight from gmem fp32
__device__ __forceinline__ void afrag_gmem(const float* xr0, const float* xr1,
                                           bool v0, bool v1, int kc,
                                           u32* ah, u32* al)
{
    float4 xa = v0 ? *reinterpret_cast<const float4*>(xr0 + 16 * kc) : make_float4(0, 0, 0, 0);
    float4 xb = v1 ? *reinterpret_cast<const float4*>(xr1 + 16 * kc) : make_float4(0, 0, 0, 0);
    ah[0] = pack_hi(xa.x, xa.y); ah[2] = pack_hi(xa.z, xa.w);
    ah[1] = pack_hi(xb.x, xb.y); ah[3] = pack_hi(xb.z, xb.w);
    al[0] = pack_lo(xa.x, xa.y); al[2] = pack_lo(xa.z, xa.w);
    al[1] = pack_lo(xb.x, xb.y); al[3] = pack_lo(xb.z, xb.w);
}

// 3-term split inner loop over NT n-tiles for one k-chunk
template <int NT>
__device__ __forceinline__ void ntile_pass(const char* wh_base, const char* wl_base,
                                           int g, int off,
                                           const u32* ah, const u32* al, float acc[][4])
{
    #pragma unroll
    for (int nt = 0; nt < NT; nt++) {
        uint2 bh = *reinterpret_cast<const uint2*>(wh_base + (nt * 8 + g) * WSTR + off);
        uint2 bl = *reinterpret_cast<const uint2*>(wl_base + (nt * 8 + g) * WSTR + off);
        u32 bhv[2] = {bh.x, bh.y}, blv[2] = {bl.x, bl.y};
        mma16816(acc[nt], ah, bhv);
        mma16816(acc[nt], ah, blv);
        mma16816(acc[nt], al, bhv);
    }
}

// ---------------- single GEMM: out = in @ W^T (+bias/relu/res) ----------------
template <int HOUT, unsigned FLAGS>
__global__ void __launch_bounds__(256) k_mma(
    const float* __restrict__ in, const float* __restrict__ W,
    const float* __restrict__ bias, const float* __restrict__ res,
    float* __restrict__ out, int nrows)
{
    const int NT = HOUT / 8;
    extern __shared__ char sm[];
    char* WH = sm;
    char* WL = sm + HOUT * WSTR;
    int tid = threadIdx.x;
    int r0 = blockIdx.x * 128;

    stage_w(W, WH, WL, HOUT, tid);
    __syncthreads();

    int w = tid >> 5, lane = tid & 31, g = lane >> 2, tg = lane & 3;
    int row0 = r0 + w * 16 + g;
    bool v0 = row0 < nrows, v1 = row0 + 8 < nrows;
    const float* xr0 = in + (size_t)row0 * 96 + 4 * tg;
    const float* xr1 = xr0 + 8 * 96;

    float acc[NT][4];
    #pragma unroll
    for (int nt = 0; nt < NT; nt++) { acc[nt][0] = acc[nt][1] = acc[nt][2] = acc[nt][3] = 0.f; }

    #pragma unroll
    for (int kc = 0; kc < 6; kc++) {
        u32 ah[4], al[4];
        afrag_gmem(xr0, xr1, v0, v1, kc, ah, al);
        ntile_pass<NT>(WH, WL, g, 32 * kc + 8 * tg, ah, al, acc);
    }

    int row1 = row0 + 8;
    #pragma unroll
    for (int nt = 0; nt < NT; nt++) {
        int n0 = nt * 8 + 2 * tg;
        float2 bv = make_float2(0.f, 0.f);
        if (FLAGS & F_BIAS) bv = *reinterpret_cast<const float2*>(bias + n0);
        if (v0) {
            float a0 = acc[nt][0] + bv.x, a1 = acc[nt][1] + bv.y;
            if (FLAGS & F_RELU) { a0 = fmaxf(a0, 0.f); a1 = fmaxf(a1, 0.f); }
            if (FLAGS & F_RES) {
                float2 rv = *reinterpret_cast<const float2*>(res + (size_t)row0 * HOUT + n0);
                a0 += rv.x; a1 += rv.y;
            }
            *reinterpret_cast<float2*>(out + (size_t)row0 * HOUT + n0) = make_float2(a0, a1);
        }
        if (v1) {
            float a0 = acc[nt][2] + bv.x, a1 = acc[nt][3] + bv.y;
            if (FLAGS & F_RELU) { a0 = fmaxf(a0, 0.f); a1 = fmaxf(a1, 0.f); }
            if (FLAGS & F_RES) {
                float2 rv = *reinterpret_cast<const float2*>(res + (size_t)row1 * HOUT + n0);
                a0 += rv.x; a1 += rv.y;
            }
            *reinterpret_cast<float2*>(out + (size_t)row1 * HOUT + n0) = make_float2(a0, a1);
        }
    }
}

// ---------------- fused post-MLP: out = relu(in@W1^T+b1)@W2^T + b2 + res ----------------
__global__ void __launch_bounds__(256) k_mma2(
    const float* __restrict__ in,
    const float* __restrict__ W1, const float* __restrict__ b1,
    const float* __restrict__ W2, const float* __restrict__ b2,
    const float* __restrict__ res, float* __restrict__ out, int nrows)
{
    const int NT = 12;
    extern __shared__ char sm[];
    char* XH  = sm;                      // 128 * 200 = 25600
    char* XL  = sm + 25600;
    char* W1H = sm + 51200;
    char* W1L = W1H + 96 * WSTR;
    char* W2H = W1L + 96 * WSTR;
    char* W2L = W2H + 96 * WSTR;         // total 128000
    int tid = threadIdx.x;
    int r0 = blockIdx.x * 128;

    stage_w(W1, W1H, W1L, 96, tid);
    stage_w(W2, W2H, W2L, 96, tid);
    __syncthreads();

    int w = tid >> 5, lane = tid & 31, g = lane >> 2, tg = lane & 3;
    int xrow = w * 16 + g;
    int row0 = r0 + xrow, row1 = row0 + 8;
    bool v0 = row0 < nrows, v1 = row1 < nrows;
    const float* xr0 = in + (size_t)row0 * 96 + 4 * tg;
    const float* xr1 = xr0 + 8 * 96;

    float acc[NT][4];
    #pragma unroll
    for (int nt = 0; nt < NT; nt++) { acc[nt][0] = acc[nt][1] = acc[nt][2] = acc[nt][3] = 0.f; }

    // stage 1: H1 = relu(in @ W1^T + b1), A-frags from gmem
    #pragma unroll
    for (int kc = 0; kc < 6; kc++) {
        u32 ah[4], al[4];
        afrag_gmem(xr0, xr1, v0, v1, kc, ah, al);
        ntile_pass<NT>(W1H, W1L, g, 32 * kc + 8 * tg, ah, al, acc);
    }

    // write H1 hi/lo into X planes (warp-private rows -> only syncwarp needed)
    #pragma unroll
    for (int nt = 0; nt < NT; nt++) {
        int n0 = nt * 8 + 2 * tg;
        float2 bv = *reinterpret_cast<const float2*>(b1 + n0);
        float a0 = fmaxf(acc[nt][0] + bv.x, 0.f), a1 = fmaxf(acc[nt][1] + bv.y, 0.f);
        float a2 = fmaxf(acc[nt][2] + bv.x, 0.f), a3 = fmaxf(acc[nt][3] + bv.y, 0.f);
        int ra = xrow * WSTR + n0 * 2;
        int rb = (xrow + 8) * WSTR + n0 * 2;
        *reinterpret_cast<u32*>(XH + ra) = pack_hi(a0, a1);
        *reinterpret_cast<u32*>(XL + ra) = pack_lo(a0, a1);
        *reinterpret_cast<u32*>(XH + rb) = pack_hi(a2, a3);
        *reinterpret_cast<u32*>(XL + rb) = pack_lo(a2, a3);
    }
    __syncwarp();

    #pragma unroll
    for (int nt = 0; nt < NT; nt++) { acc[nt][0] = acc[nt][1] = acc[nt][2] = acc[nt][3] = 0.f; }

    // stage 2: out = H1 @ W2^T + b2 + res, A-frags from smem planes
    #pragma unroll
    for (int kc = 0; kc < 6; kc++) {
        int off = 32 * kc + 8 * tg;
        uint2 pha = *reinterpret_cast<const uint2*>(XH + xrow * WSTR + off);
        uint2 phb = *reinterpret_cast<const uint2*>(XH + (xrow + 8) * WSTR + off);
        uint2 pla = *reinterpret_cast<const uint2*>(XL + xrow * WSTR + off);
        uint2 plb = *reinterpret_cast<const uint2*>(XL + (xrow + 8) * WSTR + off);
        u32 ah[4] = {pha.x, phb.x, pha.y, phb.y};
        u32 al[4] = {pla.x, plb.x, pla.y, plb.y};
        ntile_pass<NT>(W2H, W2L, g, off, ah, al, acc);
    }

    #pragma unroll
    for (int nt = 0; nt < NT; nt++) {
        int n0 = nt * 8 + 2 * tg;
        float2 bv = *reinterpret_cast<const float2*>(b2 + n0);
        if (v0) {
            float2 rv = *reinterpret_cast<const float2*>(res + (size_t)row0 * HDIM + n0);
            *reinterpret_cast<float2*>(out + (size_t)row0 * HDIM + n0) =
                make_float2(acc[nt][0] + bv.x + rv.x, acc[nt][1] + bv.y + rv.y);
        }
        if (v1) {
            float2 rv = *reinterpret_cast<const float2*>(res + (size_t)row1 * HDIM + n0);
            *reinterpret_cast<float2*>(out + (size_t)row1 * HDIM + n0) =
                make_float2(acc[nt][2] + bv.x + rv.x, acc[nt][3] + bv.y + rv.y);
        }
    }
}

// ---------------- GCN aggregation: one warp per dst node ----------------
__global__ void k_agg(const float* __restrict__ xw, const float* __restrict__ bias,
                      float* __restrict__ out)
{
    int warp = (blockIdx.x * blockDim.x + threadIdx.x) >> 5;
    int lane = threadIdx.x & 31;
    if (warp >= NNODES) return;
    int v = warp;
    int s = g_row_ptr[v], e = g_row_ptr[v + 1];
    float a0 = 0.f, a1 = 0.f, a2 = 0.f;
    int i = s;
    for (; i + 1 < e; i += 2) {
        int u0 = g_csr_src[i], u1 = g_csr_src[i + 1];
        float w0 = g_dis[u0], w1 = g_dis[u1];
        const float* r0p = xw + (size_t)u0 * HDIM;
        const float* r1p = xw + (size_t)u1 * HDIM;
        float x0 = r0p[lane], x1 = r0p[lane + 32], x2 = r0p[lane + 64];
        float y0 = r1p[lane], y1 = r1p[lane + 32], y2 = r1p[lane + 64];
        a0 += w0 * x0 + w1 * y0;
        a1 += w0 * x1 + w1 * y1;
        a2 += w0 * x2 + w1 * y2;
    }
    if (i < e) {
        int u = g_csr_src[i];
        float wn = g_dis[u];
        const float* r = xw + (size_t)u * HDIM;
        a0 += wn * r[lane];
        a1 += wn * r[lane + 32];
        a2 += wn * r[lane + 64];
    }
    float dv = g_dis[v];
    float iv = g_invdeg[v];
    const float* sr = xw + (size_t)v * HDIM;
    float* o = out + (size_t)v * HDIM;
    o[lane]      = a0 * dv + sr[lane]      * iv + bias[lane];
    o[lane + 32] = a1 * dv + sr[lane + 32] * iv + bias[lane + 32];
    o[lane + 64] = a2 * dv + sr[lane + 64] * iv + bias[lane + 64];
}

// ---------------- launch ----------------
extern "C" void kernel_launch(void* const* d_in, const int* in_sizes, int n_in,
                              void* d_out, int out_size)
{
    const float* x       = (const float*)d_in[0];
    const int*   t       = (const int*)  d_in[1];
    const int*   ei      = (const int*)  d_in[2];
    const float* emb     = (const float*)d_in[3];
    const float* fw_W    = (const float*)d_in[4];
    const float* fw_b    = (const float*)d_in[5];
    const float* pre_W   = (const float*)d_in[6];
    const float* pre_b   = (const float*)d_in[7];
    const float* conv_W  = (const float*)d_in[8];
    const float* conv_b  = (const float*)d_in[9];
    const float* post_W1 = (const float*)d_in[10];
    const float* post_b1 = (const float*)d_in[11];
    const float* post_W2 = (const float*)d_in[12];
    const float* post_b2 = (const float*)d_in[13];
    const float* fin_W   = (const float*)d_in[14];
    const float* fin_b   = (const float*)d_in[15];
    float* out = (float*)d_out;

    const int* src = ei;
    const int* dst = ei + NEDGES;

    float *A, *B, *C, *D, *Wc, *bc;
    cudaGetSymbolAddress((void**)&A,  g_bufA);
    cudaGetSymbolAddress((void**)&B,  g_bufB);
    cudaGetSymbolAddress((void**)&C,  g_bufC);
    cudaGetSymbolAddress((void**)&D,  g_bufD);
    cudaGetSymbolAddress((void**)&Wc, g_Wc);
    cudaGetSymbolAddress((void**)&bc, g_bc);

    const int SMEM96 = 2 * 96 * WSTR;                 // 38400
    const int SMEM32 = 2 * 32 * WSTR;                 // 12800
    const int SMEM2  = 2 * 128 * WSTR + 4 * 96 * WSTR; // 128000
    cudaFuncSetAttribute(k_mma<96, F_BIAS>, cudaFuncAttributeMaxDynamicSharedMemorySize, SMEM96);
    cudaFuncSetAttribute(k_mma<32, F_BIAS>, cudaFuncAttributeMaxDynamicSharedMemorySize, SMEM32);
    cudaFuncSetAttribute(k_mma2,            cudaFuncAttributeMaxDynamicSharedMemorySize, SMEM2);

    // fork: graph build on side stream, GEMM front-end on capture (null) stream
    cudaStream_t s2;
    cudaEvent_t eF, eJ;
    cudaStreamCreateWithFlags(&s2, cudaStreamNonBlocking);
    cudaEventCreateWithFlags(&eF, cudaEventDisableTiming);
    cudaEventCreateWithFlags(&eJ, cudaEventDisableTiming);

    cudaEventRecord(eF, 0);
    cudaStreamWaitEvent(s2, eF, 0);
    k_zero_deg  <<<(NNODES + 255) / 256, 256, 0, s2>>>();
    k_hist      <<<(NEDGES + 255) / 256, 256, 0, s2>>>(dst);
    k_scan_part <<<SCAN_NBLK, SCAN_B, 0, s2>>>();
    k_scan_mid  <<<1, 128, 0, s2>>>();
    k_scan_apply<<<SCAN_NBLK, SCAN_B, 0, s2>>>();
    k_scatter   <<<(NEDGES + 255) / 256, 256, 0, s2>>>(src, dst);
    cudaEventRecord(eJ, s2);

    const int GG = (NNODES + 127) / 128;
    const int AGG_BLOCKS = (NNODES * 32 + 255) / 256;

    // null stream: composes + first GEMM + layer-0 pre GEMM (independent of graph)
    k_compose2<<<dim3(HDIM, 2), HDIM>>>(pre_W, pre_b, conv_W, emb, t);
    k_mma<96, F_BIAS><<<GG, 256, SMEM96>>>(x, fw_W, fw_b, nullptr, A, NNODES);
    k_mma<96, F_BIAS><<<GG, 256, SMEM96>>>(A, Wc, bc, nullptr, C, NNODES);

    cudaStreamWaitEvent(0, eJ, 0);   // join graph build before aggregation

    // layer 0
    k_agg<<<AGG_BLOCKS, 256>>>(C, conv_b, D);
    k_mma2<<<GG, 256, SMEM2>>>(D, post_W1, post_b1, post_W2, post_b2, A, B, NNODES);

    // layer 1
    k_mma<96, F_BIAS><<<GG, 256, SMEM96>>>(B, Wc + HDIM * HDIM, bc + HDIM, nullptr, C, NNODES);
    k_agg<<<AGG_BLOCKS, 256>>>(C, conv_b + HDIM, D);
    k_mma2<<<GG, 256, SMEM2>>>(D, post_W1 + HDIM * HDIM, post_b1 + HDIM,
                               post_W2 + HDIM * HDIM, post_b2 + HDIM, B, C, NNODES);

    // final
    k_mma<32, F_BIAS><<<GG, 256, SMEM32>>>(C, fin_W, fin_b, nullptr, out, NNODES);
}

// round 8
// speedup vs baseline: 1.0285x; 1.0212x over previous
#include <cuda_runtime.h>
#include <cuda_bf16.h>
#include <cstdint>

#define NNODES 50000
#define NEDGES 800000
#define HDIM   96

typedef unsigned long long u64;
typedef unsigned int u32;

// ---------------- scratch ----------------
__device__ __align__(128) float g_bufA[NNODES * HDIM];
__device__ __align__(128) float g_bufB[NNODES * HDIM];
__device__ __align__(128) float g_bufD[NNODES * HDIM];
__device__ __align__(128) float g_Wc[2][HDIM * HDIM];
__device__ __align__(128) float g_bc[2][HDIM];
__device__ __align__(128) float g_s[NNODES];
__device__ int   g_deg[NNODES];
__device__ float g_dis[NNODES];
__device__ float g_invdeg[NNODES];
__device__ int   g_row_ptr[NNODES + 1];
__device__ int   g_cursor[NNODES];
__device__ int   g_csr_src[NEDGES];
__device__ int   g_part[128];

// ---------------- graph build ----------------
__global__ void k_zero_deg() {
    int i = blockIdx.x * blockDim.x + threadIdx.x;
    if (i < NNODES) g_deg[i] = 0;
}
__global__ void k_hist(const int* __restrict__ dst) {
    int i = blockIdx.x * blockDim.x + threadIdx.x;
    if (i < NEDGES) atomicAdd(&g_deg[dst[i]], 1);
}

#define SCAN_B 512
#define SCAN_NBLK ((NNODES + SCAN_B - 1) / SCAN_B)   // 98

__global__ void k_scan_part() {
    __shared__ int ws[16];
    int i = blockIdx.x * SCAN_B + threadIdx.x;
    int v = (i < NNODES) ? g_deg[i] : 0;
    int lane = threadIdx.x & 31, wid = threadIdx.x >> 5;
    int s = v;
    #pragma unroll
    for (int o = 16; o > 0; o >>= 1) s += __shfl_down_sync(0xffffffffu, s, o);
    if (lane == 0) ws[wid] = s;
    __syncthreads();
    if (wid == 0) {
        int t = (lane < (SCAN_B / 32)) ? ws[lane] : 0;
        #pragma unroll
        for (int o = 16; o > 0; o >>= 1) t += __shfl_down_sync(0xffffffffu, t, o);
        if (lane == 0) g_part[blockIdx.x] = t;
    }
}
__global__ void k_scan_mid() {          // 128 thr, one pass (SCAN_NBLK <= 128)
    __shared__ int ws[4];
    int lane = threadIdx.x & 31, wid = threadIdx.x >> 5;
    int i = threadIdx.x;
    int v = (i < SCAN_NBLK) ? g_part[i] : 0;
    int x = v;
    #pragma unroll
    for (int o = 1; o < 32; o <<= 1) {
        int y = __shfl_up_sync(0xffffffffu, x, o);
        if (lane >= o) x += y;
    }
    if (lane == 31) ws[wid] = x;
    __syncthreads();
    int woff = 0;
    #pragma unroll
    for (int q = 0; q < 4; q++) if (q < wid) woff += ws[q];
    if (i < SCAN_NBLK) g_part[i] = woff + x - v;
    if (i == 127) g_row_ptr[NNODES] = woff + x;
}
__global__ void k_scan_apply() {
    __shared__ int ws[17];
    int i = blockIdx.x * SCAN_B + threadIdx.x;
    int v = (i < NNODES) ? g_deg[i] : 0;
    int lane = threadIdx.x & 31, wid = threadIdx.x >> 5;
    int x = v;
    #pragma unroll
    for (int o = 1; o < 32; o <<= 1) {
        int y = __shfl_up_sync(0xffffffffu, x, o);
        if (lane >= o) x += y;
    }
    if (lane == 31) ws[wid] = x;
    __syncthreads();
    if (wid == 0) {
        int nw = SCAN_B / 32;
        int s = (lane < nw) ? ws[lane] : 0;
        #pragma unroll
        for (int o = 1; o < 32; o <<= 1) {
            int y = __shfl_up_sync(0xffffffffu, s, o);
            if (lane >= o) s += y;
        }
        if (lane < nw) ws[lane] = s;
    }
    __syncthreads();
    int excl = x - v + (wid > 0 ? ws[wid - 1] : 0) + g_part[blockIdx.x];
    if (i < NNODES) {
        g_row_ptr[i] = excl;
        g_cursor[i] = excl;
        float d = (float)(v + 1);
        g_dis[i] = rsqrtf(d);
        g_invdeg[i] = 1.0f / d;
    }
}
__global__ void k_scatter(const int* __restrict__ src, const int* __restrict__ dst) {
    int i = blockIdx.x * blockDim.x + threadIdx.x;
    if (i < NEDGES) {
        int d = dst[i];
        int p = atomicAdd(&g_cursor[d], 1);
        g_csr_src[p] = src[i];
    }
}

// ---------------- weight compose (both layers, one launch) ----------------
__global__ void k_compose2(const float* __restrict__ preW, const float* __restrict__ pre_b,
                           const float* __restrict__ convW,
                           const float* __restrict__ emb, const int* __restrict__ t)
{
    __shared__ float cw[HDIM];
    __shared__ float red[HDIM];
    int l = blockIdx.y;
    const float* pW = preW + l * HDIM * HDIM;
    const float* pb = pre_b + l * HDIM;
    const float* cW = convW + l * HDIM * HDIM;
    int j = blockIdx.x, k = threadIdx.x;
    cw[k] = cW[j * HDIM + k];
    __syncthreads();
    float acc = 0.f;
    #pragma unroll 4
    for (int m = 0; m < HDIM; m++) acc += cw[m] * pW[m * HDIM + k];
    g_Wc[l][j * HDIM + k] = acc;
    int t0 = t[0];
    red[k] = cw[k] * (pb[k] + emb[t0 * HDIM + k]);
    __syncthreads();
    if (k == 0) {
        float s = 0.f;
        for (int m = 0; m < HDIM; m++) s += red[m];
        g_bc[l][j] = s;
    }
}

// ---------------- mma.sync bf16-split GEMM pieces ----------------
enum { F_BIAS = 1 };
#define WSTR 200   // smem row stride (50 words, conflict-free)

__device__ __forceinline__ void mma16816(float* c, const u32* a, const u32* b) {
    asm volatile(
        "mma.sync.aligned.m16n8k16.row.col.f32.bf16.bf16.f32 "
        "{%0,%1,%2,%3}, {%4,%5,%6,%7}, {%8,%9}, {%0,%1,%2,%3};"
        : "+f"(c[0]), "+f"(c[1]), "+f"(c[2]), "+f"(c[3])
        : "r"(a[0]), "r"(a[1]), "r"(a[2]), "r"(a[3]), "r"(b[0]), "r"(b[1]));
}
__device__ __forceinline__ u32 pack_hi(float f0, float f1) {
    __nv_bfloat162 p;
    p.x = __float2bfloat16(f0);
    p.y = __float2bfloat16(f1);
    return *reinterpret_cast<u32*>(&p);
}
__device__ __forceinline__ u32 pack_lo(float f0, float f1) {
    __nv_bfloat162 p;
    __nv_bfloat16 h0 = __float2bfloat16(f0), h1 = __float2bfloat16(f1);
    p.x = __float2bfloat16(f0 - __bfloat162float(h0));
    p.y = __float2bfloat16(f1 - __bfloat162float(h1));
    return *reinterpret_cast<u32*>(&p);
}

__device__ __forceinline__ void stage_w(const float* __restrict__ W,
                                        char* wh, char* wl, int rows, int tid)
{
    for (int i = tid; i < rows * 24; i += 256) {
        int row = i / 24, q = i - row * 24;
        float4 v = *reinterpret_cast<const float4*>(W + row * 96 + q * 4);
        *reinterpret_cast<uint2*>(wh + row * WSTR + q * 8) =
            make_uint2(pack_hi(v.x, v.y), pack_hi(v.z, v.w));
        *reinterpret_cast<uint2*>(wl + row * WSTR + q * 8) =
            make_uint2(pack_lo(v.x, v.y), pack_lo(v.z, v.w));
    }
}

__device__ __forceinline__ void afrag_gmem(const float* xr0, const float* xr1,
                                           bool v0, bool v1, int kc,
                                           u32* ah, u32* al)
{
    float4 xa = v0 ? *reinterpret_cast<const float4*>(xr0 + 16 * kc) : make_float4(0, 0, 0, 0);
    float4 xb = v1 ? *reinterpret_cast<const float4*>(xr1 + 16 * kc) : make_float4(0, 0, 0, 0);
    ah[0] = pack_hi(xa.x, xa.y); ah[2] = pack_hi(xa.z, xa.w);
    ah[1] = pack_hi(xb.x, xb.y); ah[3] = pack_hi(xb.z, xb.w);
    al[0] = pack_lo(xa.x, xa.y); al[2] = pack_lo(xa.z, xa.w);
    al[1] = pack_lo(xb.x, xb.y); al[3] = pack_lo(xb.z, xb.w);
}

template <int NT>
__device__ __forceinline__ void ntile_pass(const char* wh_base, const char* wl_base,
                                           int g, int off,
                                           const u32* ah, const u32* al, float acc[][4])
{
    #pragma unroll
    for (int nt = 0; nt < NT; nt++) {
        uint2 bh = *reinterpret_cast<const uint2*>(wh_base + (nt * 8 + g) * WSTR + off);
        uint2 bl = *reinterpret_cast<const uint2*>(wl_base + (nt * 8 + g) * WSTR + off);
        u32 bhv[2] = {bh.x, bh.y}, blv[2] = {bl.x, bl.y};
        mma16816(acc[nt], ah, bhv);
        mma16816(acc[nt], ah, blv);
        mma16816(acc[nt], al, bhv);
    }
}

// smem-plane A-frag pass (X lives in XH/XL planes)
template <int NT>
__device__ __forceinline__ void plane_pass(const char* XH, const char* XL,
                                           const char* WH, const char* WL,
                                           int xrow, int g, int tg, float acc[][4])
{
    #pragma unroll
    for (int kc = 0; kc < 6; kc++) {
        int off = 32 * kc + 8 * tg;
        uint2 pha = *reinterpret_cast<const uint2*>(XH + xrow * WSTR + off);
        uint2 phb = *reinterpret_cast<const uint2*>(XH + (xrow + 8) * WSTR + off);
        uint2 pla = *reinterpret_cast<const uint2*>(XL + xrow * WSTR + off);
        uint2 plb = *reinterpret_cast<const uint2*>(XL + (xrow + 8) * WSTR + off);
        u32 ah[4] = {pha.x, phb.x, pha.y, phb.y};
        u32 al[4] = {pla.x, plb.x, pla.y, plb.y};
        ntile_pass<NT>(WH, WL, g, off, ah, al, acc);
    }
}

// write a warp's 2x(16-row half) results into the X planes as hi/lo bf16
__device__ __forceinline__ void planes_write(char* XH, char* XL, int xrow, int tg,
                                             int nt, float a0, float a1, float a2, float a3)
{
    int n0 = nt * 8 + 2 * tg;
    int ra = xrow * WSTR + n0 * 2;
    int rb = (xrow + 8) * WSTR + n0 * 2;
    *reinterpret_cast<u32*>(XH + ra) = pack_hi(a0, a1);
    *reinterpret_cast<u32*>(XL + ra) = pack_lo(a0, a1);
    *reinterpret_cast<u32*>(XH + rb) = pack_hi(a2, a3);
    *reinterpret_cast<u32*>(XL + rb) = pack_lo(a2, a3);
}

// ---------------- plain GEMM: out = in @ W^T + bias ----------------
template <int HOUT, unsigned FLAGS>
__global__ void __launch_bounds__(256) k_mma(
    const float* __restrict__ in, const float* __restrict__ W,
    const float* __restrict__ bias,
    float* __restrict__ out, int nrows)
{
    const int NT = HOUT / 8;
    extern __shared__ char sm[];
    char* WH = sm;
    char* WL = sm + HOUT * WSTR;
    int tid = threadIdx.x;
    int r0 = blockIdx.x * 128;

    stage_w(W, WH, WL, HOUT, tid);
    __syncthreads();

    int w = tid >> 5, lane = tid & 31, g = lane >> 2, tg = lane & 3;
    int row0 = r0 + w * 16 + g;
    bool v0 = row0 < nrows, v1 = row0 + 8 < nrows;
    const float* xr0 = in + (size_t)row0 * 96 + 4 * tg;
    const float* xr1 = xr0 + 8 * 96;

    float acc[NT][4];
    #pragma unroll
    for (int nt = 0; nt < NT; nt++) { acc[nt][0] = acc[nt][1] = acc[nt][2] = acc[nt][3] = 0.f; }

    #pragma unroll
    for (int kc = 0; kc < 6; kc++) {
        u32 ah[4], al[4];
        afrag_gmem(xr0, xr1, v0, v1, kc, ah, al);
        ntile_pass<NT>(WH, WL, g, 32 * kc + 8 * tg, ah, al, acc);
    }

    int row1 = row0 + 8;
    #pragma unroll
    for (int nt = 0; nt < NT; nt++) {
        int n0 = nt * 8 + 2 * tg;
        float2 bv = *reinterpret_cast<const float2*>(bias + n0);
        if (v0)
            *reinterpret_cast<float2*>(out + (size_t)row0 * HOUT + n0) =
                make_float2(acc[nt][0] + bv.x, acc[nt][1] + bv.y);
        if (v1)
            *reinterpret_cast<float2*>(out + (size_t)row1 * HOUT + n0) =
                make_float2(acc[nt][2] + bv.x, acc[nt][3] + bv.y);
    }
}

// ---------------- fused layer kernel ----------------
// G  = Dagg @ Wc^T + s*bc + conv_b          (agg commuted through pre+conv weights)
// H1 = relu(G @ W1^T + b1)
// H2 = H1 @ W2^T + b2 + res
// if LAST: out = H2 @ finW^T + fin_b  (32 cols) else out = H2 (96 cols)
template <bool LAST>
__global__ void __launch_bounds__(256) k_layer(
    const float* __restrict__ Dagg, const float* __restrict__ svec,
    const float* __restrict__ Wc, const float* __restrict__ bc,
    const float* __restrict__ convb,
    const float* __restrict__ W1, const float* __restrict__ b1,
    const float* __restrict__ W2, const float* __restrict__ b2,
    const float* __restrict__ res,
    const float* __restrict__ finW, const float* __restrict__ finb,
    float* __restrict__ out, int nrows)
{
    const int NT = 12;
    extern __shared__ char sm[];
    char* XH  = sm;                          // 128*200 = 25600
    char* XL  = sm + 25600;
    char* WcH = sm + 51200;
    char* WcL = WcH + 96 * WSTR;
    char* W1H = WcL + 96 * WSTR;
    char* W1L = W1H + 96 * WSTR;
    char* W2H = W1L + 96 * WSTR;
    char* W2L = W2H + 96 * WSTR;             // end 166400
    char* FH  = W2L + 96 * WSTR;             // LAST only: +6400
    char* FL  = FH + 32 * WSTR;              // +6400 -> 179200
    int tid = threadIdx.x;
    int r0 = blockIdx.x * 128;

    stage_w(Wc, WcH, WcL, 96, tid);
    stage_w(W1, W1H, W1L, 96, tid);
    stage_w(W2, W2H, W2L, 96, tid);
    if (LAST) stage_w(finW, FH, FL, 32, tid);
    __syncthreads();

    int w = tid >> 5, lane = tid & 31, g = lane >> 2, tg = lane & 3;
    int xrow = w * 16 + g;
    int row0 = r0 + xrow, row1 = row0 + 8;
    bool v0 = row0 < nrows, v1 = row1 < nrows;
    const float* xr0 = Dagg + (size_t)row0 * 96 + 4 * tg;
    const float* xr1 = xr0 + 8 * 96;
    float s0 = v0 ? svec[row0] : 0.f;
    float s1 = v1 ? svec[row1] : 0.f;

    float acc[NT][4];
    #pragma unroll
    for (int nt = 0; nt < NT; nt++) { acc[nt][0] = acc[nt][1] = acc[nt][2] = acc[nt][3] = 0.f; }

    // stage 0: G = Dagg @ Wc^T + s*bc + conv_b
    #pragma unroll
    for (int kc = 0; kc < 6; kc++) {
        u32 ah[4], al[4];
        afrag_gmem(xr0, xr1, v0, v1, kc, ah, al);
        ntile_pass<NT>(WcH, WcL, g, 32 * kc + 8 * tg, ah, al, acc);
    }
    __syncwarp();
    #pragma unroll
    for (int nt = 0; nt < NT; nt++) {
        int n0 = nt * 8 + 2 * tg;
        float2 bcv = *reinterpret_cast<const float2*>(bc + n0);
        float2 cbv = *reinterpret_cast<const float2*>(convb + n0);
        planes_write(XH, XL, xrow, tg, nt,
                     acc[nt][0] + s0 * bcv.x + cbv.x, acc[nt][1] + s0 * bcv.y + cbv.y,
                     acc[nt][2] + s1 * bcv.x + cbv.x, acc[nt][3] + s1 * bcv.y + cbv.y);
        acc[nt][0] = acc[nt][1] = acc[nt][2] = acc[nt][3] = 0.f;
    }
    __syncwarp();

    // stage 1: H1 = relu(G @ W1^T + b1)
    plane_pass<NT>(XH, XL, W1H, W1L, xrow, g, tg, acc);
    __syncwarp();
    #pragma unroll
    for (int nt = 0; nt < NT; nt++) {
        int n0 = nt * 8 + 2 * tg;
        float2 bv = *reinterpret_cast<const float2*>(b1 + n0);
        planes_write(XH, XL, xrow, tg, nt,
                     fmaxf(acc[nt][0] + bv.x, 0.f), fmaxf(acc[nt][1] + bv.y, 0.f),
                     fmaxf(acc[nt][2] + bv.x, 0.f), fmaxf(acc[nt][3] + bv.y, 0.f));
        acc[nt][0] = acc[nt][1] = acc[nt][2] = acc[nt][3] = 0.f;
    }
    __syncwarp();

    // stage 2: H2 = H1 @ W2^T + b2 + res
    plane_pass<NT>(XH, XL, W2H, W2L, xrow, g, tg, acc);
    __syncwarp();

    if (!LAST) {
        #pragma unroll
        for (int nt = 0; nt < NT; nt++) {
            int n0 = nt * 8 + 2 * tg;
            float2 bv = *reinterpret_cast<const float2*>(b2 + n0);
            if (v0) {
                float2 rv = *reinterpret_cast<const float2*>(res + (size_t)row0 * HDIM + n0);
                *reinterpret_cast<float2*>(out + (size_t)row0 * HDIM + n0) =
                    make_float2(acc[nt][0] + bv.x + rv.x, acc[nt][1] + bv.y + rv.y);
            }
            if (v1) {
                float2 rv = *reinterpret_cast<const float2*>(res + (size_t)row1 * HDIM + n0);
                *reinterpret_cast<float2*>(out + (size_t)row1 * HDIM + n0) =
                    make_float2(acc[nt][2] + bv.x + rv.x, acc[nt][3] + bv.y + rv.y);
            }
        }
    } else {
        // write H2 into planes, then stage 3: out = H2 @ finW^T + fin_b (32 cols)
        #pragma unroll
        for (int nt = 0; nt < NT; nt++) {
            int n0 = nt * 8 + 2 * tg;
            float2 bv = *reinterpret_cast<const float2*>(b2 + n0);
            float2 rv0 = v0 ? *reinterpret_cast<const float2*>(res + (size_t)row0 * HDIM + n0)
                            : make_float2(0.f, 0.f);
            float2 rv1 = v1 ? *reinterpret_cast<const float2*>(res + (size_t)row1 * HDIM + n0)
                            : make_float2(0.f, 0.f);
            planes_write(XH, XL, xrow, tg, nt,
                         acc[nt][0] + bv.x + rv0.x, acc[nt][1] + bv.y + rv0.y,
                         acc[nt][2] + bv.x + rv1.x, acc[nt][3] + bv.y + rv1.y);
        }
        __syncwarp();
        float facc[4][4];
        #pragma unroll
        for (int nt = 0; nt < 4; nt++) { facc[nt][0] = facc[nt][1] = facc[nt][2] = facc[nt][3] = 0.f; }
        plane_pass<4>(XH, XL, FH, FL, xrow, g, tg, facc);
        #pragma unroll
        for (int nt = 0; nt < 4; nt++) {
            int n0 = nt * 8 + 2 * tg;
            float2 bv = *reinterpret_cast<const float2*>(finb + n0);
            if (v0)
                *reinterpret_cast<float2*>(out + (size_t)row0 * 32 + n0) =
                    make_float2(facc[nt][0] + bv.x, facc[nt][1] + bv.y);
            if (v1)
                *reinterpret_cast<float2*>(out + (size_t)row1 * 32 + n0) =
                    make_float2(facc[nt][2] + bv.x, facc[nt][3] + bv.y);
        }
    }
}

// ---------------- GCN aggregation (no weights): one warp per dst node ----------------
// Dagg[v] = dis[v]*sum_e dis[src]*P[src] + P[v]*invdeg[v];  s[v] = dis[v]*sum_e dis[src] + invdeg[v]
__global__ void k_agg(const float* __restrict__ P, float* __restrict__ out,
                      float* __restrict__ s_out)
{
    int warp = (blockIdx.x * blockDim.x + threadIdx.x) >> 5;
    int lane = threadIdx.x & 31;
    if (warp >= NNODES) return;
    int v = warp;
    int s = g_row_ptr[v], e = g_row_ptr[v + 1];
    float a0 = 0.f, a1 = 0.f, a2 = 0.f, wsum = 0.f;
    int i = s;
    for (; i + 1 < e; i += 2) {
        int u0 = g_csr_src[i], u1 = g_csr_src[i + 1];
        float w0 = g_dis[u0], w1 = g_dis[u1];
        const float* r0p = P + (size_t)u0 * HDIM;
        const float* r1p = P + (size_t)u1 * HDIM;
        float x0 = r0p[lane], x1 = r0p[lane + 32], x2 = r0p[lane + 64];
        float y0 = r1p[lane], y1 = r1p[lane + 32], y2 = r1p[lane + 64];
        a0 += w0 * x0 + w1 * y0;
        a1 += w0 * x1 + w1 * y1;
        a2 += w0 * x2 + w1 * y2;
        wsum += w0 + w1;
    }
    if (i < e) {
        int u = g_csr_src[i];
        float wn = g_dis[u];
        const float* r = P + (size_t)u * HDIM;
        a0 += wn * r[lane];
        a1 += wn * r[lane + 32];
        a2 += wn * r[lane + 64];
        wsum += wn;
    }
    float dv = g_dis[v];
    float iv = g_invdeg[v];
    const float* sr = P + (size_t)v * HDIM;
    float* o = out + (size_t)v * HDIM;
    o[lane]      = a0 * dv + sr[lane]      * iv;
    o[lane + 32] = a1 * dv + sr[lane + 32] * iv;
    o[lane + 64] = a2 * dv + sr[lane + 64] * iv;
    if (lane == 0) s_out[v] = dv * wsum + iv;
}

// ---------------- launch ----------------
extern "C" void kernel_launch(void* const* d_in, const int* in_sizes, int n_in,
                              void* d_out, int out_size)
{
    const float* x       = (const float*)d_in[0];
    const int*   t       = (const int*)  d_in[1];
    const int*   ei      = (const int*)  d_in[2];
    const float* emb     = (const float*)d_in[3];
    const float* fw_W    = (const float*)d_in[4];
    const float* fw_b    = (const float*)d_in[5];
    const float* pre_W   = (const float*)d_in[6];
    const float* pre_b   = (const float*)d_in[7];
    const float* conv_W  = (const float*)d_in[8];
    const float* conv_b  = (const float*)d_in[9];
    const float* post_W1 = (const float*)d_in[10];
    const float* post_b1 = (const float*)d_in[11];
    const float* post_W2 = (const float*)d_in[12];
    const float* post_b2 = (const float*)d_in[13];
    const float* fin_W   = (const float*)d_in[14];
    const float* fin_b   = (const float*)d_in[15];
    float* out = (float*)d_out;

    const int* src = ei;
    const int* dst = ei + NEDGES;

    float *A, *B, *D, *Wc, *bc, *S;
    cudaGetSymbolAddress((void**)&A,  g_bufA);
    cudaGetSymbolAddress((void**)&B,  g_bufB);
    cudaGetSymbolAddress((void**)&D,  g_bufD);
    cudaGetSymbolAddress((void**)&Wc, g_Wc);
    cudaGetSymbolAddress((void**)&bc, g_bc);
    cudaGetSymbolAddress((void**)&S,  g_s);

    const int SMEM96 = 2 * 96 * WSTR;                   // 38400
    const int SMEML0 = 2 * 128 * WSTR + 6 * 96 * WSTR;  // 166400
    const int SMEML1 = SMEML0 + 2 * 32 * WSTR;          // 179200
    cudaFuncSetAttribute(k_mma<96, F_BIAS>, cudaFuncAttributeMaxDynamicSharedMemorySize, SMEM96);
    cudaFuncSetAttribute(k_layer<false>,    cudaFuncAttributeMaxDynamicSharedMemorySize, SMEML0);
    cudaFuncSetAttribute(k_layer<true>,     cudaFuncAttributeMaxDynamicSharedMemorySize, SMEML1);

    // fork: graph build on side stream, GEMM front-end on capture (null) stream
    cudaStream_t s2;
    cudaEvent_t eF, eJ;
    cudaStreamCreateWithFlags(&s2, cudaStreamNonBlocking);
    cudaEventCreateWithFlags(&eF, cudaEventDisableTiming);
    cudaEventCreateWithFlags(&eJ, cudaEventDisableTiming);

    cudaEventRecord(eF, 0);
    cudaStreamWaitEvent(s2, eF, 0);
    k_zero_deg  <<<(NNODES + 255) / 256, 256, 0, s2>>>();
    k_hist      <<<(NEDGES + 255) / 256, 256, 0, s2>>>(dst);
    k_scan_part <<<SCAN_NBLK, SCAN_B, 0, s2>>>();
    k_scan_mid  <<<1, 128, 0, s2>>>();
    k_scan_apply<<<SCAN_NBLK, SCAN_B, 0, s2>>>();
    k_scatter   <<<(NEDGES + 255) / 256, 256, 0, s2>>>(src, dst);
    cudaEventRecord(eJ, s2);

    const int GG = (NNODES + 127) / 128;
    const int AGG_BLOCKS = (NNODES * 32 + 255) / 256;

    // null stream: compose + first-layer GEMM (independent of graph)
    k_compose2<<<dim3(HDIM, 2), HDIM>>>(pre_W, pre_b, conv_W, emb, t);
    k_mma<96, F_BIAS><<<GG, 256, SMEM96>>>(x, fw_W, fw_b, A, NNODES);

    cudaStreamWaitEvent(0, eJ, 0);   // join graph build

    // layer 0: agg first (commuted), then fused Wc+postMLP
    k_agg<<<AGG_BLOCKS, 256>>>(A, D, S);
    k_layer<false><<<GG, 256, SMEML0>>>(D, S, Wc, bc, conv_b,
                                        post_W1, post_b1, post_W2, post_b2,
                                        A, nullptr, nullptr, B, NNODES);

    // layer 1 (+ final GEMM fused)
    k_agg<<<AGG_BLOCKS, 256>>>(B, D, S);
    k_layer<true><<<GG, 256, SMEML1>>>(D, S, Wc + HDIM * HDIM, bc + HDIM, conv_b + HDIM,
                                       post_W1 + HDIM * HDIM, post_b1 + HDIM,
                                       post_W2 + HDIM * HDIM, post_b2 + HDIM,
                                       B, fin_W, fin_b, out, NNODES);
}